// round 1
// baseline (speedup 1.0000x reference)
#include <cuda_runtime.h>

namespace {
constexpr int NB = 128;    // batch
constexpr int NT = 256;    // time
constexpr int NI = 1024;   // input dim
constexpr int NK = 128;    // num tags
}

__device__ float g_logits[NB * NT * NK];
__device__ float g_llh[NB];

__device__ __forceinline__ unsigned long long pk2(float x) {
    unsigned long long r;
    asm("mov.b64 %0, {%1, %1};" : "=l"(r) : "f"(x));
    return r;
}
__device__ __forceinline__ void fma2(unsigned long long& d, unsigned long long a, unsigned long long b) {
    asm("fma.rn.f32x2 %0, %1, %2, %0;" : "+l"(d) : "l"(a), "l"(b));
}

// ---------------------------------------------------------------------------
// GEMM: g_logits[r][c] = sum_k H[r][k]*W[k][c] + bias[c] + (1-mask[r])*(-1e32)
// 128x128 tile, BK=16, 256 threads, 8x8 per thread, packed f32x2 FMA.
// ---------------------------------------------------------------------------
__global__ __launch_bounds__(256, 2) void gemm_kernel(
    const float* __restrict__ H, const float* __restrict__ W,
    const float* __restrict__ bias, const int* __restrict__ mask)
{
    __shared__ __align__(16) float As[16][132];   // As[k][row]
    __shared__ __align__(16) float Bs[16][128];   // Bs[k][col]

    const int tid  = threadIdx.x;
    const int row0 = blockIdx.x * 128;
    const int tx   = tid & 15;
    const int ty   = tid >> 4;

    unsigned long long acc[8][4];
#pragma unroll
    for (int i = 0; i < 8; ++i)
#pragma unroll
        for (int j = 0; j < 4; ++j) acc[i][j] = 0ull;

    for (int kk = 0; kk < NI; kk += 16) {
        // load H tile (128 rows x 16 k) transposed into As[k][row]
#pragma unroll
        for (int u = 0; u < 2; ++u) {
            int f4 = tid * 2 + u;
            int r = f4 >> 2, q = f4 & 3;
            float4 v = *reinterpret_cast<const float4*>(H + (row0 + r) * NI + kk + q * 4);
            As[q * 4 + 0][r] = v.x;
            As[q * 4 + 1][r] = v.y;
            As[q * 4 + 2][r] = v.z;
            As[q * 4 + 3][r] = v.w;
        }
        // load W tile (16 k x 128 cols)
#pragma unroll
        for (int u = 0; u < 2; ++u) {
            int f4 = tid * 2 + u;
            int k = f4 >> 5, c4 = f4 & 31;
            float4 v = *reinterpret_cast<const float4*>(W + (kk + k) * NK + c4 * 4);
            *reinterpret_cast<float4*>(&Bs[k][c4 * 4]) = v;
        }
        __syncthreads();
#pragma unroll
        for (int k = 0; k < 16; ++k) {
            float4 a0 = *reinterpret_cast<const float4*>(&As[k][ty * 8]);
            float4 a1 = *reinterpret_cast<const float4*>(&As[k][ty * 8 + 4]);
            ulonglong2 b0 = *reinterpret_cast<const ulonglong2*>(&Bs[k][tx * 8]);
            ulonglong2 b1 = *reinterpret_cast<const ulonglong2*>(&Bs[k][tx * 8 + 4]);
            float av[8] = {a0.x, a0.y, a0.z, a0.w, a1.x, a1.y, a1.z, a1.w};
#pragma unroll
            for (int r = 0; r < 8; ++r) {
                unsigned long long a2 = pk2(av[r]);
                fma2(acc[r][0], a2, b0.x);
                fma2(acc[r][1], a2, b0.y);
                fma2(acc[r][2], a2, b1.x);
                fma2(acc[r][3], a2, b1.y);
            }
        }
        __syncthreads();
    }

    float bv[8];
#pragma unroll
    for (int c = 0; c < 8; ++c) bv[c] = bias[tx * 8 + c];

#pragma unroll
    for (int rr = 0; rr < 8; ++rr) {
        int r = row0 + ty * 8 + rr;
        float madd = (1.0f - (float)mask[r]) * -1e32f;
        float ob[8];
#pragma unroll
        for (int pp = 0; pp < 4; ++pp) {
            unsigned long long v = acc[rr][pp];
            float lo = __uint_as_float((unsigned)(v & 0xffffffffull));
            float hi = __uint_as_float((unsigned)(v >> 32));
            ob[pp * 2]     = lo + bv[pp * 2] + madd;
            ob[pp * 2 + 1] = hi + bv[pp * 2 + 1] + madd;
        }
        float* o = g_logits + r * NK + tx * 8;
        *reinterpret_cast<float4*>(o)     = make_float4(ob[0], ob[1], ob[2], ob[3]);
        *reinterpret_cast<float4*>(o + 4) = make_float4(ob[4], ob[5], ob[6], ob[7]);
    }
}

// ---------------------------------------------------------------------------
// CRF recurrence: one CTA per batch. Threads 0..127 = viterbi(j), 128..255 = alpha(j).
// alpha logsumexp via precomputed exp(tr): a'_j = m + log(sum_i exp(a_i-m)*etr_ij) + e_j
// Backpointers live in shared; backtrace, num, den, llh all in epilogue.
// Dynamic smem: trT(128x132) + etrT(128x132) + sv(2x128) + aa(2x128) + p(128)
//               + red(256) floats, then bp(255x128 u8) + tags(256 int) = 172416 B
// ---------------------------------------------------------------------------
__global__ __launch_bounds__(256, 1) void crf_kernel(
    const int* __restrict__ mask, const int* __restrict__ labels,
    const float* __restrict__ st, const float* __restrict__ et,
    const float* __restrict__ tr, float* __restrict__ out)
{
    extern __shared__ __align__(16) float sm[];
    float* trT  = sm;                    // [128][132], trT[j][i] = tr[i][j]
    float* etrT = trT + 128 * 132;       // exp(tr) transposed
    float* sv   = etrT + 128 * 132;      // viterbi scores, double buffered
    float* aa   = sv + 256;              // alpha scores, double buffered
    float* p    = aa + 256;              // exp weights
    float* red  = p + 128;               // reduction scratch (256)
    unsigned char* bp = (unsigned char*)(red + 256);   // [255][128]
    int* tags = (int*)(bp + 255 * 128);  // [256]

    __shared__ float s_den, s_num;
    __shared__ int s_last;

    const int tid = threadIdx.x;
    const int b   = blockIdx.x;
    const int jj  = tid & 127;
    const bool isv = tid < 128;

    for (int idx = tid; idx < NK * NK; idx += 256) {
        int i = idx >> 7, j = idx & 127;
        float v = tr[idx];
        trT[j * 132 + i]  = v;
        etrT[j * 132 + i] = __expf(v);
    }
    if (tid < NK) {
        float s0 = st[tid] + g_logits[b * NT * NK + tid];
        sv[tid] = s0;
        aa[tid] = s0;
    }
    __syncthreads();

    for (int t = 1; t < NT; ++t) {
        const int cur = (t - 1) & 1, nx = t & 1;
        const float* svc = sv + cur * 128;
        const float* ac  = aa + cur * 128;
        float e = g_logits[(b * NT + t) * NK + jj];
        int mt  = mask[b * NT + t];
        float best = -3.4e38f;
        int bi = 0;
        if (isv) {
            const float4* s4 = reinterpret_cast<const float4*>(svc);
            const float4* t4 = reinterpret_cast<const float4*>(trT + jj * 132);
#pragma unroll
            for (int i = 0; i < 32; ++i) {
                float4 s = s4[i], q = t4[i];
                float c0 = s.x + q.x; if (c0 > best) { best = c0; bi = 4 * i; }
                float c1 = s.y + q.y; if (c1 > best) { best = c1; bi = 4 * i + 1; }
                float c2 = s.z + q.z; if (c2 > best) { best = c2; bi = 4 * i + 2; }
                float c3 = s.w + q.w; if (c3 > best) { best = c3; bi = 4 * i + 3; }
            }
        } else {
            p[jj] = __expf(ac[jj] - ac[0]);   // spread across j is bounded (~±10)
        }
        __syncthreads();
        if (isv) {
            float nv = best + e;
            sv[nx * 128 + jj] = mt ? nv : svc[jj];
            bp[(t - 1) * 128 + jj] = (unsigned char)(mt ? bi : jj);
        } else {
            const float4* p4 = reinterpret_cast<const float4*>(p);
            const float4* e4 = reinterpret_cast<const float4*>(etrT + jj * 132);
            float d0 = 0.f, d1 = 0.f, d2 = 0.f, d3 = 0.f;
#pragma unroll
            for (int i = 0; i < 32; ++i) {
                float4 pv = p4[i], ev = e4[i];
                d0 += pv.x * ev.x; d1 += pv.y * ev.y;
                d2 += pv.z * ev.z; d3 += pv.w * ev.w;
            }
            float dot = (d0 + d1) + (d2 + d3);
            float na  = ac[0] + __logf(dot) + e;
            aa[nx * 128 + jj] = mt ? na : ac[jj];
        }
        __syncthreads();
    }

    const float* svF = sv + ((NT - 1) & 1) * 128;
    const float* aF  = aa + ((NT - 1) & 1) * 128;

    // den = logsumexp(aF + et); last = first-argmax(svF + et)
    if (tid < 128) red[tid] = aF[tid] + et[tid];
    __syncthreads();
    if (tid == 0) {
        float m = red[0];
        for (int i = 1; i < 128; ++i) m = fmaxf(m, red[i]);
        float ssum = 0.f;
        for (int i = 0; i < 128; ++i) ssum += __expf(red[i] - m);
        s_den = m + __logf(ssum);
        float bb = svF[0] + et[0];
        int bl = 0;
        for (int i = 1; i < 128; ++i) {
            float c = svF[i] + et[i];
            if (c > bb) { bb = c; bl = i; }
        }
        s_last = bl;
    }
    __syncthreads();
    if (tid == 0) {
        int cur = s_last;
        for (int s = NT - 2; s >= 0; --s) { tags[s + 1] = cur; cur = bp[s * 128 + cur]; }
        tags[0] = cur;
    }
    __syncthreads();

    // decoded output (as float)
    out[b * NT + tid] = (float)tags[tid];

    // numerator: parallel over t, tree-reduced (deterministic fixed order)
    {
        int lt = labels[b * NT + tid];
        float contrib;
        if (tid == 0) {
            contrib = st[lt] + g_logits[b * NT * NK + lt];
        } else {
            int lp = labels[b * NT + tid - 1];
            float mf = (float)mask[b * NT + tid];
            contrib = (trT[lt * 132 + lp] + g_logits[(b * NT + tid) * NK + lt]) * mf;
        }
        red[tid] = contrib;
    }
    __syncthreads();
    for (int s = 128; s > 0; s >>= 1) {
        if (tid < s) red[tid] += red[tid + s];
        __syncthreads();
    }
    if (tid == 0) s_num = red[0];
    __syncthreads();
    red[tid] = (float)mask[b * NT + tid];
    __syncthreads();
    for (int s = 128; s > 0; s >>= 1) {
        if (tid < s) red[tid] += red[tid + s];
        __syncthreads();
    }
    if (tid == 0) {
        int send = (int)red[0] - 1;             // seq_end = sum(mask) - 1
        int lend = labels[b * NT + send];
        g_llh[b] = (s_num + et[lend]) - s_den;
    }
}

__global__ void finalize_kernel(float* __restrict__ out, int out_size) {
    __shared__ float r[128];
    int t = threadIdx.x;
    r[t] = g_llh[t];
    __syncthreads();
    for (int s = 64; s > 0; s >>= 1) {
        if (t < s) r[t] += r[t + s];
        __syncthreads();
    }
    if (t == 0) out[out_size - 1] = -r[0];
}

extern "C" void kernel_launch(void* const* d_in, const int* in_sizes, int n_in,
                              void* d_out, int out_size) {
    const float* H     = (const float*)d_in[0];   // hiddens (128,256,1024)
    const int*   mask  = (const int*)  d_in[1];   // (128,256)
    const int*   labels= (const int*)  d_in[2];   // (128,256)
    const float* W     = (const float*)d_in[3];   // (1024,128)
    const float* bias  = (const float*)d_in[4];   // (128,)
    const float* st    = (const float*)d_in[5];   // (128,)
    const float* et    = (const float*)d_in[6];   // (128,)
    const float* tr    = (const float*)d_in[7];   // (128,128)
    float* out = (float*)d_out;

    constexpr int CRF_SMEM = (128 * 132 * 2 + 2 * 128 + 2 * 128 + 128 + 256) * 4
                           + 255 * 128 + 256 * 4;   // 172416 bytes
    cudaFuncSetAttribute(crf_kernel, cudaFuncAttributeMaxDynamicSharedMemorySize, CRF_SMEM);

    gemm_kernel<<<(NB * NT) / 128, 256>>>(H, W, bias, mask);
    crf_kernel<<<NB, 256, CRF_SMEM>>>(mask, labels, st, et, tr, out);
    finalize_kernel<<<1, 128>>>(out, out_size);
}

// round 2
// speedup vs baseline: 1.0606x; 1.0606x over previous
#include <cuda_runtime.h>

namespace {
constexpr int NB = 128;    // batch
constexpr int NT = 256;    // time
constexpr int NI = 1024;   // input dim
constexpr int NK = 128;    // num tags
}

__device__ float g_logits[NB * NT * NK];
__device__ float g_llh[NB];

__device__ __forceinline__ unsigned long long pk2(float x) {
    unsigned long long r;
    asm("mov.b64 %0, {%1, %1};" : "=l"(r) : "f"(x));
    return r;
}
__device__ __forceinline__ unsigned long long pk2b(float lo, float hi) {
    unsigned long long r;
    asm("mov.b64 %0, {%1, %2};" : "=l"(r) : "f"(lo), "f"(hi));
    return r;
}
__device__ __forceinline__ void up2(unsigned long long v, float& lo, float& hi) {
    asm("mov.b64 {%0, %1}, %2;" : "=f"(lo), "=f"(hi) : "l"(v));
}
__device__ __forceinline__ void fma2(unsigned long long& d, unsigned long long a, unsigned long long b) {
    asm("fma.rn.f32x2 %0, %1, %2, %0;" : "+l"(d) : "l"(a), "l"(b));
}
__device__ __forceinline__ unsigned long long add2(unsigned long long a, unsigned long long b) {
    unsigned long long r;
    asm("add.rn.f32x2 %0, %1, %2;" : "=l"(r) : "l"(a), "l"(b));
    return r;
}

// ---------------------------------------------------------------------------
// GEMM: 64x128 tile, BK=16, 128 threads, 8x8 per thread, packed f32x2 FMA.
// 512 CTAs, 4 CTAs/SM -> one full wave.
// ---------------------------------------------------------------------------
__global__ __launch_bounds__(128, 4) void gemm_kernel(
    const float* __restrict__ H, const float* __restrict__ W,
    const float* __restrict__ bias, const int* __restrict__ mask)
{
    __shared__ __align__(16) float As[16][68];    // As[k][row], 64 rows
    __shared__ __align__(16) float Bs[16][128];   // Bs[k][col]

    const int tid  = threadIdx.x;
    const int row0 = blockIdx.x * 64;
    const int tx   = tid & 15;
    const int ty   = tid >> 4;    // 0..7

    unsigned long long acc[8][4];
#pragma unroll
    for (int i = 0; i < 8; ++i)
#pragma unroll
        for (int j = 0; j < 4; ++j) acc[i][j] = 0ull;

    for (int kk = 0; kk < NI; kk += 16) {
        // A tile: 64 rows x 16 k -> As[k][row] transposed. 256 float4, 2/thread.
#pragma unroll
        for (int u = 0; u < 2; ++u) {
            int f4 = tid * 2 + u;
            int r = f4 >> 2, q = f4 & 3;
            float4 v = *reinterpret_cast<const float4*>(H + (row0 + r) * NI + kk + q * 4);
            As[q * 4 + 0][r] = v.x;
            As[q * 4 + 1][r] = v.y;
            As[q * 4 + 2][r] = v.z;
            As[q * 4 + 3][r] = v.w;
        }
        // B tile: 16 k x 128 cols. 512 float4, 4/thread.
#pragma unroll
        for (int u = 0; u < 4; ++u) {
            int f4 = tid * 4 + u;
            int k = f4 >> 5, c4 = f4 & 31;
            float4 v = *reinterpret_cast<const float4*>(W + (kk + k) * NK + c4 * 4);
            *reinterpret_cast<float4*>(&Bs[k][c4 * 4]) = v;
        }
        __syncthreads();
#pragma unroll
        for (int k = 0; k < 16; ++k) {
            float4 a0 = *reinterpret_cast<const float4*>(&As[k][ty * 8]);
            float4 a1 = *reinterpret_cast<const float4*>(&As[k][ty * 8 + 4]);
            ulonglong2 b0 = *reinterpret_cast<const ulonglong2*>(&Bs[k][tx * 8]);
            ulonglong2 b1 = *reinterpret_cast<const ulonglong2*>(&Bs[k][tx * 8 + 4]);
            float av[8] = {a0.x, a0.y, a0.z, a0.w, a1.x, a1.y, a1.z, a1.w};
#pragma unroll
            for (int r = 0; r < 8; ++r) {
                unsigned long long a2 = pk2(av[r]);
                fma2(acc[r][0], a2, b0.x);
                fma2(acc[r][1], a2, b0.y);
                fma2(acc[r][2], a2, b1.x);
                fma2(acc[r][3], a2, b1.y);
            }
        }
        __syncthreads();
    }

    float bv[8];
#pragma unroll
    for (int c = 0; c < 8; ++c) bv[c] = bias[tx * 8 + c];

#pragma unroll
    for (int rr = 0; rr < 8; ++rr) {
        int r = row0 + ty * 8 + rr;
        float madd = (1.0f - (float)mask[r]) * -1e32f;
        float ob[8];
#pragma unroll
        for (int pp = 0; pp < 4; ++pp) {
            float lo, hi;
            up2(acc[rr][pp], lo, hi);
            ob[pp * 2]     = lo + bv[pp * 2] + madd;
            ob[pp * 2 + 1] = hi + bv[pp * 2 + 1] + madd;
        }
        float* o = g_logits + r * NK + tx * 8;
        *reinterpret_cast<float4*>(o)     = make_float4(ob[0], ob[1], ob[2], ob[3]);
        *reinterpret_cast<float4*>(o + 4) = make_float4(ob[4], ob[5], ob[6], ob[7]);
    }
}

// ---------------------------------------------------------------------------
// CRF: one CTA (512 threads) per batch.
//   tid 0..255   : viterbi group, thread (j = gt>>1, h = gt&1) owns tr[i][j]
//                  for i in [h*64, h*64+64) IN REGISTERS (packed f32x2).
//                  Max only (no index). Scores history in smem. 1 named bar/step.
//   tid 256..511 : alpha group, same split with exp(tr) in registers.
//                  2 named bars/step.
// Backtrace reconstructs argmax along the path only (warp 0, exact fp32 replay,
// first-index tie semantics via ballot+ffs).
// ---------------------------------------------------------------------------
__device__ __forceinline__ int argred32(float bv, int bi) {
    unsigned u = __float_as_uint(bv);
    unsigned key = u ^ ((unsigned)(((int)u) >> 31) | 0x80000000u);  // order-preserving
    unsigned mx = __reduce_max_sync(0xffffffffu, key);
    unsigned bal = __ballot_sync(0xffffffffu, key == mx);
    int ldr = __ffs(bal) - 1;
    return __shfl_sync(0xffffffffu, bi, ldr);
}

__global__ __launch_bounds__(512, 1) void crf_kernel(
    const int* __restrict__ mask, const int* __restrict__ labels,
    const float* __restrict__ st, const float* __restrict__ et,
    const float* __restrict__ tr, float* __restrict__ out)
{
    extern __shared__ __align__(16) float sm[];
    float* trT  = sm;                    // [128][132]  trT[j][i] = tr[i][j]
    float* svh  = trT + 128 * 132;       // [256][128]  viterbi score history
    float* aa   = svh + 256 * 128;       // [2][128]    alpha double buffer
    float* p    = aa + 256;              // [128]       exp weights
    float* ets  = p + 128;               // [128]       end_transitions
    float* red  = ets + 128;             // [512]       reduction scratch
    int*   msk  = (int*)(red + 512);     // [256]
    int*   tags = msk + 256;             // [256]

    __shared__ float s_den, s_num;

    const int tid = threadIdx.x;
    const int b   = blockIdx.x;
    const bool isv = tid < 256;
    const int gt = isv ? tid : tid - 256;
    const int j  = gt >> 1;
    const int h  = gt & 1;

    // --- one-time loads ---
    for (int idx = tid; idx < NK * NK; idx += 512) {
        int i = idx >> 7, jj = idx & 127;
        trT[jj * 132 + i] = tr[idx];
    }
    for (int idx = tid; idx < NT; idx += 512) msk[idx] = mask[b * NT + idx];
    if (tid < NK) ets[tid] = et[tid];

    // transition half-column in registers (packed pairs)
    unsigned long long trp[32];
#pragma unroll
    for (int q = 0; q < 32; ++q) {
        float v0 = tr[(h * 64 + 2 * q) * NK + j];
        float v1 = tr[(h * 64 + 2 * q + 1) * NK + j];
        if (!isv) { v0 = __expf(v0); v1 = __expf(v1); }
        trp[q] = pk2b(v0, v1);
    }

    if (h == 0) {
        float s0 = st[j] + g_logits[b * NT * NK + j];
        if (isv) svh[j] = s0;
        else     aa[j]  = s0;
    }
    __syncthreads();

    // --- main recurrence, logits prefetched one step ahead ---
    float e_cur = g_logits[(b * NT + 1) * NK + j];
    for (int t = 1; t < NT; ++t) {
        const int cur = (t - 1) & 1, nx = t & 1;
        const float e = e_cur;
        if (t + 1 < NT) e_cur = g_logits[(b * NT + t + 1) * NK + j];
        const int mt = msk[t];

        if (isv) {
            const ulonglong2* s4 = reinterpret_cast<const ulonglong2*>(svh + (t - 1) * NK + h * 64);
            float b0 = -3.402823466e38f, b1 = b0, b2 = b0, b3 = b0;
#pragma unroll
            for (int q = 0; q < 16; ++q) {
                ulonglong2 sp = s4[q];
                unsigned long long c01 = add2(sp.x, trp[2 * q]);
                unsigned long long c23 = add2(sp.y, trp[2 * q + 1]);
                float l0, h0, l1, h1;
                up2(c01, l0, h0); up2(c23, l1, h1);
                b0 = fmaxf(b0, l0); b1 = fmaxf(b1, h0);
                b2 = fmaxf(b2, l1); b3 = fmaxf(b3, h1);
            }
            float bvv = fmaxf(fmaxf(b0, b1), fmaxf(b2, b3));
            bvv = fmaxf(bvv, __shfl_xor_sync(0xffffffffu, bvv, 1));
            if (h == 0) svh[t * NK + j] = mt ? (bvv + e) : svh[(t - 1) * NK + j];
            asm volatile("bar.sync 1, 256;" ::: "memory");
        } else {
            float a0 = aa[cur * NK];
            if (h == 0) p[j] = __expf(aa[cur * NK + j] - a0);
            asm volatile("bar.sync 2, 256;" ::: "memory");
            const ulonglong2* p4 = reinterpret_cast<const ulonglong2*>(p + h * 64);
            unsigned long long d01 = 0ull, d23 = 0ull;
#pragma unroll
            for (int q = 0; q < 16; ++q) {
                ulonglong2 pv = p4[q];
                fma2(d01, pv.x, trp[2 * q]);
                fma2(d23, pv.y, trp[2 * q + 1]);
            }
            float s0, s1, s2, s3;
            up2(d01, s0, s1); up2(d23, s2, s3);
            float dot = (s0 + s1) + (s2 + s3);
            dot += __shfl_xor_sync(0xffffffffu, dot, 1);
            if (h == 0) aa[nx * NK + j] = mt ? (a0 + __logf(dot) + e) : aa[cur * NK + j];
            asm volatile("bar.sync 2, 256;" ::: "memory");
        }
    }
    __syncthreads();

    // --- backtrace (warp 0): exact replay argmax along path only ---
    if (tid < 32) {
        const int lane = tid;
        float4 sv4 = *reinterpret_cast<const float4*>(svh + 255 * NK + lane * 4);
        float4 ee4 = *reinterpret_cast<const float4*>(ets + lane * 4);
        float c0 = sv4.x + ee4.x, c1 = sv4.y + ee4.y, c2 = sv4.z + ee4.z, c3 = sv4.w + ee4.w;
        float bvv = c0; int bi = lane * 4;
        if (c1 > bvv) { bvv = c1; bi = lane * 4 + 1; }
        if (c2 > bvv) { bvv = c2; bi = lane * 4 + 2; }
        if (c3 > bvv) { bvv = c3; bi = lane * 4 + 3; }
        int curtag = argred32(bvv, bi);
        for (int t = NT - 1; t >= 1; --t) {
            if (lane == 0) tags[t] = curtag;
            if (msk[t]) {
                float4 s4 = *reinterpret_cast<const float4*>(svh + (t - 1) * NK + lane * 4);
                float4 t4 = *reinterpret_cast<const float4*>(trT + curtag * 132 + lane * 4);
                c0 = s4.x + t4.x; c1 = s4.y + t4.y; c2 = s4.z + t4.z; c3 = s4.w + t4.w;
                bvv = c0; bi = lane * 4;
                if (c1 > bvv) { bvv = c1; bi = lane * 4 + 1; }
                if (c2 > bvv) { bvv = c2; bi = lane * 4 + 2; }
                if (c3 > bvv) { bvv = c3; bi = lane * 4 + 3; }
                curtag = argred32(bvv, bi);
            }
        }
        if (lane == 0) tags[0] = curtag;
    }
    // --- den (thread 256, runs concurrently with backtrace) ---
    if (tid == 256) {
        const float* aF = aa + 128;   // final buffer: nx at t=255 is 1
        float m = -3.402823466e38f;
        for (int i = 0; i < NK; ++i) m = fmaxf(m, aF[i] + ets[i]);
        float ssum = 0.f;
        for (int i = 0; i < NK; ++i) ssum += __expf(aF[i] + ets[i] - m);
        s_den = m + __logf(ssum);
    }
    __syncthreads();

    if (tid < 256) out[b * NT + tid] = (float)tags[tid];

    // --- numerator (threads 0..255 contribute, 512-wide tree reduce) ---
    float contrib = 0.f;
    if (tid < 256) {
        int lt = labels[b * NT + tid];
        if (tid == 0) {
            contrib = st[lt] + g_logits[b * NT * NK + lt];
        } else {
            int lp = labels[b * NT + tid - 1];
            contrib = (trT[lt * 132 + lp] + g_logits[(b * NT + tid) * NK + lt]) * (float)msk[tid];
        }
    }
    red[tid] = contrib;
    __syncthreads();
    for (int s = 256; s > 0; s >>= 1) {
        if (tid < s) red[tid] += red[tid + s];
        __syncthreads();
    }
    if (tid == 0) s_num = red[0];
    __syncthreads();
    red[tid] = (tid < 256) ? (float)msk[tid] : 0.f;
    __syncthreads();
    for (int s = 256; s > 0; s >>= 1) {
        if (tid < s) red[tid] += red[tid + s];
        __syncthreads();
    }
    if (tid == 0) {
        int send = (int)red[0] - 1;
        int lend = labels[b * NT + send];
        g_llh[b] = (s_num + ets[lend]) - s_den;
    }
}

__global__ void finalize_kernel(float* __restrict__ out, int out_size) {
    __shared__ float r[128];
    int t = threadIdx.x;
    r[t] = g_llh[t];
    __syncthreads();
    for (int s = 64; s > 0; s >>= 1) {
        if (t < s) r[t] += r[t + s];
        __syncthreads();
    }
    if (t == 0) out[out_size - 1] = -r[0];
}

extern "C" void kernel_launch(void* const* d_in, const int* in_sizes, int n_in,
                              void* d_out, int out_size) {
    const float* H     = (const float*)d_in[0];   // hiddens (128,256,1024)
    const int*   mask  = (const int*)  d_in[1];   // (128,256)
    const int*   labels= (const int*)  d_in[2];   // (128,256)
    const float* W     = (const float*)d_in[3];   // (1024,128)
    const float* bias  = (const float*)d_in[4];   // (128,)
    const float* st    = (const float*)d_in[5];   // (128,)
    const float* et    = (const float*)d_in[6];   // (128,)
    const float* tr    = (const float*)d_in[7];   // (128,128)
    float* out = (float*)d_out;

    // trT(128*132) + svh(256*128) + aa(256) + p(128) + ets(128) + red(512) floats
    // + msk(256) + tags(256) ints
    constexpr int CRF_SMEM = (128 * 132 + 256 * 128 + 256 + 128 + 128 + 512) * 4
                           + (256 + 256) * 4;   // 204800 + 2048 = 206848 bytes
    cudaFuncSetAttribute(crf_kernel, cudaFuncAttributeMaxDynamicSharedMemorySize, CRF_SMEM);

    gemm_kernel<<<(NB * NT) / 64, 128>>>(H, W, bias, mask);
    crf_kernel<<<NB, 512, CRF_SMEM>>>(mask, labels, st, et, tr, out);
    finalize_kernel<<<1, 128>>>(out, out_size);
}

// round 4
// speedup vs baseline: 1.0623x; 1.0015x over previous
#include <cuda_runtime.h>

namespace {
constexpr int NB = 128;    // batch
constexpr int NT = 256;    // time
constexpr int NI = 1024;   // input dim
constexpr int NK = 128;    // num tags
}

__device__ float g_logits[NB * NT * NK];
__device__ float g_llh[NB];

__device__ __forceinline__ unsigned long long pk2(float x) {
    unsigned long long r;
    asm("mov.b64 %0, {%1, %1};" : "=l"(r) : "f"(x));
    return r;
}
__device__ __forceinline__ unsigned long long pk2b(float lo, float hi) {
    unsigned long long r;
    asm("mov.b64 %0, {%1, %2};" : "=l"(r) : "f"(lo), "f"(hi));
    return r;
}
__device__ __forceinline__ void up2(unsigned long long v, float& lo, float& hi) {
    asm("mov.b64 {%0, %1}, %2;" : "=f"(lo), "=f"(hi) : "l"(v));
}
__device__ __forceinline__ void fma2(unsigned long long& d, unsigned long long a, unsigned long long b) {
    asm("fma.rn.f32x2 %0, %1, %2, %0;" : "+l"(d) : "l"(a), "l"(b));
}
__device__ __forceinline__ unsigned long long add2(unsigned long long a, unsigned long long b) {
    unsigned long long r;
    asm("add.rn.f32x2 %0, %1, %2;" : "=l"(r) : "l"(a), "l"(b));
    return r;
}

// ---------------------------------------------------------------------------
// GEMM: 64x128 tile, BK=16, 128 threads, 8x8 per thread, packed f32x2 FMA.
// 512 CTAs, 4 CTAs/SM -> one full wave.
// ---------------------------------------------------------------------------
__global__ __launch_bounds__(128, 4) void gemm_kernel(
    const float* __restrict__ H, const float* __restrict__ W,
    const float* __restrict__ bias, const int* __restrict__ mask)
{
    __shared__ __align__(16) float As[16][68];    // As[k][row], 64 rows
    __shared__ __align__(16) float Bs[16][128];   // Bs[k][col]

    const int tid  = threadIdx.x;
    const int row0 = blockIdx.x * 64;
    const int tx   = tid & 15;
    const int ty   = tid >> 4;    // 0..7

    unsigned long long acc[8][4];
#pragma unroll
    for (int i = 0; i < 8; ++i)
#pragma unroll
        for (int j = 0; j < 4; ++j) acc[i][j] = 0ull;

    for (int kk = 0; kk < NI; kk += 16) {
        // A tile: 64 rows x 16 k -> As[k][row] transposed. 256 float4, 2/thread.
#pragma unroll
        for (int u = 0; u < 2; ++u) {
            int f4 = tid * 2 + u;
            int r = f4 >> 2, q = f4 & 3;
            float4 v = *reinterpret_cast<const float4*>(H + (row0 + r) * NI + kk + q * 4);
            As[q * 4 + 0][r] = v.x;
            As[q * 4 + 1][r] = v.y;
            As[q * 4 + 2][r] = v.z;
            As[q * 4 + 3][r] = v.w;
        }
        // B tile: 16 k x 128 cols. 512 float4, 4/thread.
#pragma unroll
        for (int u = 0; u < 4; ++u) {
            int f4 = tid * 4 + u;
            int k = f4 >> 5, c4 = f4 & 31;
            float4 v = *reinterpret_cast<const float4*>(W + (kk + k) * NK + c4 * 4);
            *reinterpret_cast<float4*>(&Bs[k][c4 * 4]) = v;
        }
        __syncthreads();
#pragma unroll
        for (int k = 0; k < 16; ++k) {
            float4 a0 = *reinterpret_cast<const float4*>(&As[k][ty * 8]);
            float4 a1 = *reinterpret_cast<const float4*>(&As[k][ty * 8 + 4]);
            ulonglong2 b0 = *reinterpret_cast<const ulonglong2*>(&Bs[k][tx * 8]);
            ulonglong2 b1 = *reinterpret_cast<const ulonglong2*>(&Bs[k][tx * 8 + 4]);
            float av[8] = {a0.x, a0.y, a0.z, a0.w, a1.x, a1.y, a1.z, a1.w};
#pragma unroll
            for (int r = 0; r < 8; ++r) {
                unsigned long long a2 = pk2(av[r]);
                fma2(acc[r][0], a2, b0.x);
                fma2(acc[r][1], a2, b0.y);
                fma2(acc[r][2], a2, b1.x);
                fma2(acc[r][3], a2, b1.y);
            }
        }
        __syncthreads();
    }

    float bv[8];
#pragma unroll
    for (int c = 0; c < 8; ++c) bv[c] = bias[tx * 8 + c];

#pragma unroll
    for (int rr = 0; rr < 8; ++rr) {
        int r = row0 + ty * 8 + rr;
        float madd = (1.0f - (float)mask[r]) * -1e32f;
        float ob[8];
#pragma unroll
        for (int pp = 0; pp < 4; ++pp) {
            float lo, hi;
            up2(acc[rr][pp], lo, hi);
            ob[pp * 2]     = lo + bv[pp * 2] + madd;
            ob[pp * 2 + 1] = hi + bv[pp * 2 + 1] + madd;
        }
        float* o = g_logits + r * NK + tx * 8;
        *reinterpret_cast<float4*>(o)     = make_float4(ob[0], ob[1], ob[2], ob[3]);
        *reinterpret_cast<float4*>(o + 4) = make_float4(ob[4], ob[5], ob[6], ob[7]);
    }
}

// ---------------------------------------------------------------------------
// CRF: one CTA (512 threads) per batch.
//   tid 0..255   : viterbi group, thread (j = gt>>1, h = gt&1) owns tr[i][j]
//                  for i in [h*64, h*64+64) IN REGISTERS (packed f32x2).
//                  Max only (no index). Scores history in smem. 1 named bar/step.
//   tid 256..511 : alpha group, same split with exp(tr) in registers.
//                  2 named bars/step.
// Backtrace reconstructs argmax along the path only (warp 0, exact fp32 replay,
// first-index tie semantics via ballot+ffs).
// ---------------------------------------------------------------------------
__device__ __forceinline__ int argred32(float bv, int bi) {
    unsigned u = __float_as_uint(bv);
    unsigned key = u ^ ((unsigned)(((int)u) >> 31) | 0x80000000u);  // order-preserving
    unsigned mx = __reduce_max_sync(0xffffffffu, key);
    unsigned bal = __ballot_sync(0xffffffffu, key == mx);
    int ldr = __ffs(bal) - 1;
    return __shfl_sync(0xffffffffu, bi, ldr);
}

__global__ __launch_bounds__(512, 1) void crf_kernel(
    const int* __restrict__ mask, const int* __restrict__ labels,
    const float* __restrict__ st, const float* __restrict__ et,
    const float* __restrict__ tr, float* __restrict__ out)
{
    extern __shared__ __align__(16) float sm[];
    float* trT  = sm;                    // [128][132]  trT[j][i] = tr[i][j]
    float* svh  = trT + 128 * 132;       // [256][128]  viterbi score history
    float* aa   = svh + 256 * 128;       // [2][128]    alpha double buffer
    float* p    = aa + 256;              // [128]       exp weights
    float* ets  = p + 128;               // [128]       end_transitions
    float* red  = ets + 128;             // [512]       reduction scratch
    int*   msk  = (int*)(red + 512);     // [256]
    int*   tags = msk + 256;             // [256]

    __shared__ float s_den, s_num;

    const int tid = threadIdx.x;
    const int b   = blockIdx.x;
    const bool isv = tid < 256;
    const int gt = isv ? tid : tid - 256;
    const int j  = gt >> 1;
    const int h  = gt & 1;

    // --- one-time loads ---
    for (int idx = tid; idx < NK * NK; idx += 512) {
        int i = idx >> 7, jj = idx & 127;
        trT[jj * 132 + i] = tr[idx];
    }
    for (int idx = tid; idx < NT; idx += 512) msk[idx] = mask[b * NT + idx];
    if (tid < NK) ets[tid] = et[tid];

    // transition half-column in registers (packed pairs)
    unsigned long long trp[32];
#pragma unroll
    for (int q = 0; q < 32; ++q) {
        float v0 = tr[(h * 64 + 2 * q) * NK + j];
        float v1 = tr[(h * 64 + 2 * q + 1) * NK + j];
        if (!isv) { v0 = __expf(v0); v1 = __expf(v1); }
        trp[q] = pk2b(v0, v1);
    }

    if (h == 0) {
        float s0 = st[j] + g_logits[b * NT * NK + j];
        if (isv) svh[j] = s0;
        else     aa[j]  = s0;
    }
    __syncthreads();

    // --- main recurrence, logits prefetched one step ahead ---
    float e_cur = g_logits[(b * NT + 1) * NK + j];
    for (int t = 1; t < NT; ++t) {
        const int cur = (t - 1) & 1, nx = t & 1;
        const float e = e_cur;
        if (t + 1 < NT) e_cur = g_logits[(b * NT + t + 1) * NK + j];
        const int mt = msk[t];

        if (isv) {
            const ulonglong2* s4 = reinterpret_cast<const ulonglong2*>(svh + (t - 1) * NK + h * 64);
            float b0 = -3.402823466e38f, b1 = b0, b2 = b0, b3 = b0;
#pragma unroll
            for (int q = 0; q < 16; ++q) {
                ulonglong2 sp = s4[q];
                unsigned long long c01 = add2(sp.x, trp[2 * q]);
                unsigned long long c23 = add2(sp.y, trp[2 * q + 1]);
                float l0, h0, l1, h1;
                up2(c01, l0, h0); up2(c23, l1, h1);
                b0 = fmaxf(b0, l0); b1 = fmaxf(b1, h0);
                b2 = fmaxf(b2, l1); b3 = fmaxf(b3, h1);
            }
            float bvv = fmaxf(fmaxf(b0, b1), fmaxf(b2, b3));
            bvv = fmaxf(bvv, __shfl_xor_sync(0xffffffffu, bvv, 1));
            if (h == 0) svh[t * NK + j] = mt ? (bvv + e) : svh[(t - 1) * NK + j];
            asm volatile("bar.sync 1, 256;" ::: "memory");
        } else {
            float a0 = aa[cur * NK];
            if (h == 0) p[j] = __expf(aa[cur * NK + j] - a0);
            asm volatile("bar.sync 2, 256;" ::: "memory");
            const ulonglong2* p4 = reinterpret_cast<const ulonglong2*>(p + h * 64);
            unsigned long long d01 = 0ull, d23 = 0ull;
#pragma unroll
            for (int q = 0; q < 16; ++q) {
                ulonglong2 pv = p4[q];
                fma2(d01, pv.x, trp[2 * q]);
                fma2(d23, pv.y, trp[2 * q + 1]);
            }
            float s0, s1, s2, s3;
            up2(d01, s0, s1); up2(d23, s2, s3);
            float dot = (s0 + s1) + (s2 + s3);
            dot += __shfl_xor_sync(0xffffffffu, dot, 1);
            if (h == 0) aa[nx * NK + j] = mt ? (a0 + __logf(dot) + e) : aa[cur * NK + j];
            asm volatile("bar.sync 2, 256;" ::: "memory");
        }
    }
    __syncthreads();

    // --- backtrace (warp 0): exact replay argmax along path only ---
    if (tid < 32) {
        const int lane = tid;
        float4 sv4 = *reinterpret_cast<const float4*>(svh + 255 * NK + lane * 4);
        float4 ee4 = *reinterpret_cast<const float4*>(ets + lane * 4);
        float c0 = sv4.x + ee4.x, c1 = sv4.y + ee4.y, c2 = sv4.z + ee4.z, c3 = sv4.w + ee4.w;
        float bvv = c0; int bi = lane * 4;
        if (c1 > bvv) { bvv = c1; bi = lane * 4 + 1; }
        if (c2 > bvv) { bvv = c2; bi = lane * 4 + 2; }
        if (c3 > bvv) { bvv = c3; bi = lane * 4 + 3; }
        int curtag = argred32(bvv, bi);
        for (int t = NT - 1; t >= 1; --t) {
            if (lane == 0) tags[t] = curtag;
            if (msk[t]) {
                float4 s4 = *reinterpret_cast<const float4*>(svh + (t - 1) * NK + lane * 4);
                float4 t4 = *reinterpret_cast<const float4*>(trT + curtag * 132 + lane * 4);
                c0 = s4.x + t4.x; c1 = s4.y + t4.y; c2 = s4.z + t4.z; c3 = s4.w + t4.w;
                bvv = c0; bi = lane * 4;
                if (c1 > bvv) { bvv = c1; bi = lane * 4 + 1; }
                if (c2 > bvv) { bvv = c2; bi = lane * 4 + 2; }
                if (c3 > bvv) { bvv = c3; bi = lane * 4 + 3; }
                curtag = argred32(bvv, bi);
            }
        }
        if (lane == 0) tags[0] = curtag;
    }
    // --- den (thread 256, runs concurrently with backtrace) ---
    if (tid == 256) {
        const float* aF = aa + 128;   // final buffer: nx at t=255 is 1
        float m = -3.402823466e38f;
        for (int i = 0; i < NK; ++i) m = fmaxf(m, aF[i] + ets[i]);
        float ssum = 0.f;
        for (int i = 0; i < NK; ++i) ssum += __expf(aF[i] + ets[i] - m);
        s_den = m + __logf(ssum);
    }
    __syncthreads();

    if (tid < 256) out[b * NT + tid] = (float)tags[tid];

    // --- numerator (threads 0..255 contribute, 512-wide tree reduce) ---
    float contrib = 0.f;
    if (tid < 256) {
        int lt = labels[b * NT + tid];
        if (tid == 0) {
            contrib = st[lt] + g_logits[b * NT * NK + lt];
        } else {
            int lp = labels[b * NT + tid - 1];
            contrib = (trT[lt * 132 + lp] + g_logits[(b * NT + tid) * NK + lt]) * (float)msk[tid];
        }
    }
    red[tid] = contrib;
    __syncthreads();
    for (int s = 256; s > 0; s >>= 1) {
        if (tid < s) red[tid] += red[tid + s];
        __syncthreads();
    }
    if (tid == 0) s_num = red[0];
    __syncthreads();
    red[tid] = (tid < 256) ? (float)msk[tid] : 0.f;
    __syncthreads();
    for (int s = 256; s > 0; s >>= 1) {
        if (tid < s) red[tid] += red[tid + s];
        __syncthreads();
    }
    if (tid == 0) {
        int send = (int)red[0] - 1;
        int lend = labels[b * NT + send];
        g_llh[b] = (s_num + ets[lend]) - s_den;
    }
}

__global__ void finalize_kernel(float* __restrict__ out, int out_size) {
    __shared__ float r[128];
    int t = threadIdx.x;
    r[t] = g_llh[t];
    __syncthreads();
    for (int s = 64; s > 0; s >>= 1) {
        if (t < s) r[t] += r[t + s];
        __syncthreads();
    }
    if (t == 0) out[out_size - 1] = -r[0];
}

extern "C" void kernel_launch(void* const* d_in, const int* in_sizes, int n_in,
                              void* d_out, int out_size) {
    const float* H     = (const float*)d_in[0];   // hiddens (128,256,1024)
    const int*   mask  = (const int*)  d_in[1];   // (128,256)
    const int*   labels= (const int*)  d_in[2];   // (128,256)
    const float* W     = (const float*)d_in[3];   // (1024,128)
    const float* bias  = (const float*)d_in[4];   // (128,)
    const float* st    = (const float*)d_in[5];   // (128,)
    const float* et    = (const float*)d_in[6];   // (128,)
    const float* tr    = (const float*)d_in[7];   // (128,128)
    float* out = (float*)d_out;

    // trT(128*132) + svh(256*128) + aa(256) + p(128) + ets(128) + red(512) floats
    // + msk(256) + tags(256) ints
    constexpr int CRF_SMEM = (128 * 132 + 256 * 128 + 256 + 128 + 128 + 512) * 4
                           + (256 + 256) * 4;   // 204800 + 2048 = 206848 bytes
    cudaFuncSetAttribute(crf_kernel, cudaFuncAttributeMaxDynamicSharedMemorySize, CRF_SMEM);

    gemm_kernel<<<(NB * NT) / 64, 128>>>(H, W, bias, mask);
    crf_kernel<<<NB, 512, CRF_SMEM>>>(mask, labels, st, et, tr, out);
    finalize_kernel<<<1, 128>>>(out, out_size);
}